// round 10
// baseline (speedup 1.0000x reference)
#include <cuda_runtime.h>
#include <cstdint>

#define BATCH 4
#define CH    64
#define HH    128
#define WW    128
#define NST   16
#define NTOK  (BATCH*HH*WW)

// ---- scratch (static __device__, allocation-free) ----
__device__ float g_xT[NTOK*CH];   // x transposed, channels-last [tok][c]
__device__ float g_dp[NTOK*CH];   // delta, channels-last [tok][c]
__device__ float g_du[NTOK*CH];   // delta*u
__device__ float g_bc[NTOK*32];   // [tok][Bc(16) | Cc(16)]
__device__ float g_yh[NTOK*CH];   // horizontal scan output
__device__ float g_yv[NTOK*CH];   // vertical scan output

__device__ __forceinline__ float ex2f(float x){
    float r; asm("ex2.approx.ftz.f32 %0, %1;" : "=f"(r) : "f"(x)); return r;
}
__device__ __forceinline__ void cp16(void* dst, const void* src){
    unsigned s = (unsigned)__cvta_generic_to_shared(dst);
    asm volatile("cp.async.cg.shared.global [%0], [%1], 16;\n" :: "r"(s), "l"(src));
}
// ---- packed f32x2 helpers ----
__device__ __forceinline__ unsigned long long pk2(float lo, float hi){
    unsigned long long r; asm("mov.b64 %0, {%1,%2};" : "=l"(r) : "f"(lo), "f"(hi)); return r;
}
__device__ __forceinline__ void upk2(float& lo, float& hi, unsigned long long v){
    asm("mov.b64 {%0,%1}, %2;" : "=f"(lo), "=f"(hi) : "l"(v));
}
__device__ __forceinline__ unsigned long long mul2(unsigned long long a, unsigned long long b){
    unsigned long long r; asm("mul.rn.f32x2 %0, %1, %2;" : "=l"(r) : "l"(a), "l"(b)); return r;
}
__device__ __forceinline__ unsigned long long fmap2(unsigned long long a, unsigned long long b, unsigned long long c){
    unsigned long long r; asm("fma.rn.f32x2 %0, %1, %2, %3;" : "=l"(r) : "l"(a), "l"(b), "l"(c)); return r;
}
__device__ __forceinline__ unsigned long long addp2(unsigned long long a, unsigned long long b){
    unsigned long long r; asm("add.rn.f32x2 %0, %1, %2;" : "=l"(r) : "l"(a), "l"(b)); return r;
}

// ============================================================================
// K0: transpose x[B,C,H*W] -> g_xT[tok][c]. Both sides coalesced via smem.
// Block: 64c x 64hw tile, 256 threads. Grid: B * (HW/64) = 1024.
// ============================================================================
__global__ __launch_bounds__(256) void k_xpose(const float* __restrict__ x)
{
    __shared__ float sm[64][65];
    const int tid = threadIdx.x;
    const int blk = blockIdx.x;               // b*256 + chunk
    const int b   = blk >> 8;
    const int hw0 = (blk & 255) * 64;
    const long base = (long)b*CH*HH*WW;

    #pragma unroll
    for (int i = tid; i < 64*64; i += 256){
        int c = i >> 6, hw = i & 63;          // lanes: consecutive hw -> coalesced
        sm[hw][c] = x[base + (long)c*HH*WW + hw0 + hw];
    }
    __syncthreads();
    #pragma unroll
    for (int i = tid; i < 64*64; i += 256){
        int hw = i >> 6, c = i & 63;          // lanes: consecutive c -> coalesced
        g_xT[((long)b*HH*WW + hw0 + hw)*CH + c] = sm[hw][c];
    }
}

// ============================================================================
// K1: projection + delta. Thread = 1 token, 36 accumulators.
//     u read as 16 contiguous LDG.128 from g_xT (no smem staging, no barriers
//     in the loop). Weights broadcast from smem.
// ============================================================================
__global__ __launch_bounds__(128) void k_prep(
    const float* __restrict__ xw,   // [36][64]
    const float* __restrict__ dtw,  // [64][4]
    const float* __restrict__ dtb)  // [64]
{
    __shared__ __align__(16) float wsm[CH][36];   // [c][p] 9KB
    __shared__ float dtwT[4*CH];                  // [r][d]
    __shared__ float dtb_sm[CH];

    const int tid = threadIdx.x;
    const long tok = (long)blockIdx.x * 128 + tid;

    // ---- stage weights ----
    for (int i = tid; i < 36*CH; i += 128){
        int p = i >> 6, c = i & 63;
        wsm[c][p] = xw[i];
    }
    for (int i = tid; i < CH*4; i += 128){
        int d = i >> 2, r = i & 3;
        dtwT[r*CH + d] = dtw[i];
    }
    if (tid < CH) dtb_sm[tid] = dtb[tid];
    __syncthreads();

    // ---- GEMM: 36 outputs for own token ----
    const float4* up = reinterpret_cast<const float4*>(g_xT + tok*CH);
    float acc[36];
    #pragma unroll
    for (int p = 0; p < 36; ++p) acc[p] = 0.f;

    #pragma unroll 4
    for (int ch = 0; ch < 16; ++ch){
        float4 u4 = up[ch];                   // contiguous, own token
        #pragma unroll
        for (int cc = 0; cc < 4; ++cc){
            int c = ch*4 + cc;
            float uv = (&u4.x)[cc];
            const float4* wr = reinterpret_cast<const float4*>(&wsm[c][0]);
            #pragma unroll
            for (int q = 0; q < 9; ++q){
                float4 v = wr[q];
                acc[4*q+0] = fmaf(uv, v.x, acc[4*q+0]);
                acc[4*q+1] = fmaf(uv, v.y, acc[4*q+1]);
                acc[4*q+2] = fmaf(uv, v.z, acc[4*q+2]);
                acc[4*q+3] = fmaf(uv, v.w, acc[4*q+3]);
            }
        }
    }

    // ---- Bc|Cc straight from regs (thread owns contiguous 128B) ----
    {
        float4* bco = reinterpret_cast<float4*>(g_bc + tok*32);
        #pragma unroll
        for (int j = 0; j < 8; ++j)
            bco[j] = make_float4(acc[4+4*j], acc[5+4*j], acc[6+4*j], acc[7+4*j]);
    }

    // ---- delta = softplus(dt_raw @ dtw^T + b); du = delta*u ----
    {
        const float dt0 = acc[0], dt1 = acc[1], dt2 = acc[2], dt3 = acc[3];
        float4* dpw = reinterpret_cast<float4*>(g_dp + tok*CH);
        float4* duw = reinterpret_cast<float4*>(g_du + tok*CH);
        #pragma unroll 4
        for (int ch = 0; ch < 16; ++ch){
            float4 u4 = up[ch];               // L1 hit (just read above)
            float4 dp4, du4;
            #pragma unroll
            for (int cc = 0; cc < 4; ++cc){
                int c = ch*4 + cc;
                float pre = fmaf(dt3, dtwT[192+c],
                            fmaf(dt2, dtwT[128+c],
                            fmaf(dt1, dtwT[ 64+c],
                            fmaf(dt0, dtwT[c], dtb_sm[c]))));
                float e = __expf(-fabsf(pre));
                float delta = __logf(1.f + e) + fmaxf(pre, 0.f);
                (&dp4.x)[cc] = delta;
                (&du4.x)[cc] = delta * (&u4.x)[cc];
            }
            dpw[ch] = dp4;
            duw[ch] = du4;
        }
    }
}

// ============================================================================
// K2: selective scan, packed f32x2 math. Block = 1 sequence (64 threads,
// thread = channel). blocks 0..511 horizontal, 512..1023 vertical.
// ============================================================================
__global__ __launch_bounds__(64) void k_scan(const float* __restrict__ A_log)
{
    // 2 buffers x (16 tok x (64 dp + 64 du + 32 bc)) = 2*2560 floats = 20KB
    __shared__ __align__(16) float sm[2*2560];

    const int tid = threadIdx.x;            // channel
    const int S   = blockIdx.x;
    const int vert = (S >= 512);
    const int s    = vert ? S - 512 : S;
    const int b = s >> 7, r = s & 127;

    long tok0; int tstride;
    if (!vert){ tok0 = ((long)b*HH + r)*WW; tstride = 1;  }
    else      { tok0 = (long)b*HH*WW + r;   tstride = WW; }
    float* yout = vert ? g_yv : g_yh;

    // A with log2(e) folded in, packed in pairs: dA = exp2(delta * A2[n])
    unsigned long long A2p[8], hsp[8];
    #pragma unroll
    for (int j = 0; j < 8; ++j){
        float alo = -__expf(A_log[tid*NST + 2*j    ]) * 1.4426950408889634f;
        float ahi = -__expf(A_log[tid*NST + 2*j + 1]) * 1.4426950408889634f;
        A2p[j] = pk2(alo, ahi);
        hsp[j] = 0ull;
    }

    auto issue = [&](int t, int bufidx){
        float* dst = sm + bufidx*2560;
        const int tn = t*16;
        for (int k = tid; k < 256; k += 64){
            int l = k >> 4, q = k & 15;
            long tok = tok0 + (long)(tn + l)*tstride;
            cp16(dst +        l*64 + q*4, g_dp + tok*64 + q*4);
            cp16(dst + 1024 + l*64 + q*4, g_du + tok*64 + q*4);
        }
        for (int k = tid; k < 128; k += 64){
            int l = k >> 3, q = k & 7;
            long tok = tok0 + (long)(tn + l)*tstride;
            cp16(dst + 2048 + l*32 + q*4, g_bc + tok*32 + q*4);
        }
    };

    issue(0, 0);
    asm volatile("cp.async.commit_group;\n");

    for (int t = 0; t < 8; ++t){
        if (t < 7) issue(t+1, (t+1)&1);
        asm volatile("cp.async.commit_group;\n");
        asm volatile("cp.async.wait_group 1;\n");
        __syncthreads();

        const float* bp = sm + (t&1)*2560;
        #pragma unroll 2
        for (int l = 0; l < 16; ++l){
            float delta = bp[l*64 + tid];
            float duv   = bp[1024 + l*64 + tid];
            unsigned long long d2  = pk2(delta, delta);
            unsigned long long uv2 = pk2(duv, duv);

            const ulonglong2* q16 = reinterpret_cast<const ulonglong2*>(bp + 2048 + l*32);
            ulonglong2 B01 = q16[0], B23 = q16[1], B45 = q16[2], B67 = q16[3];
            ulonglong2 C01 = q16[4], C23 = q16[5], C45 = q16[6], C67 = q16[7];
            unsigned long long bn2[8] = {B01.x,B01.y,B23.x,B23.y,B45.x,B45.y,B67.x,B67.y};
            unsigned long long cn2[8] = {C01.x,C01.y,C23.x,C23.y,C45.x,C45.y,C67.x,C67.y};

            unsigned long long ya0=0ull, ya1=0ull, ya2=0ull, ya3=0ull;
            #pragma unroll
            for (int j = 0; j < 8; ++j){
                unsigned long long xa = mul2(d2, A2p[j]);
                float lo, hi; upk2(lo, hi, xa);
                unsigned long long dA2 = pk2(ex2f(lo), ex2f(hi));
                unsigned long long db  = mul2(uv2, bn2[j]);
                hsp[j] = fmap2(dA2, hsp[j], db);
                unsigned long long* ya = (j&2) ? ((j&1)? &ya3 : &ya2)
                                               : ((j&1)? &ya1 : &ya0);
                *ya = fmap2(hsp[j], cn2[j], *ya);
            }
            unsigned long long sA = addp2(ya0, ya1);
            unsigned long long sB = addp2(ya2, ya3);
            unsigned long long sT = addp2(sA, sB);
            float slo, shi; upk2(slo, shi, sT);
            yout[(tok0 + (long)(t*16 + l)*tstride)*64 + tid] = slo + shi;  // coalesced
        }
        __syncthreads();
    }
}

// ============================================================================
// K3: out[b,c,h,w] = y_h + y_v + 2*D[c]*x  (smem transpose for coalescing)
// ============================================================================
__global__ __launch_bounds__(256) void k_comb(
    const float* __restrict__ x, const float* __restrict__ Dp,
    float* __restrict__ out)
{
    __shared__ float sm[CH*33];
    const int tid = threadIdx.x;
    const int blk = blockIdx.x;                 // b*512 + h*4 + wt
    const int wt = blk & 3, h = (blk >> 2) & 127, b = blk >> 9;
    const int w0 = wt * 32;
    const long tokb = ((long)b*HH + h)*WW + w0;

    for (int i = tid; i < 32*CH; i += 256){
        int w = i >> 6, c = i & 63;
        long o = (tokb + w)*CH + c;             // lanes = consecutive c -> coalesced
        sm[c*33 + w] = g_yh[o] + g_yv[o];
    }
    __syncthreads();
    for (int i = tid; i < CH*32; i += 256){
        int c = i >> 5, w = i & 31;
        long a = (((long)b*CH + c)*HH + h)*WW + w0 + w;  // lanes = consecutive w
        out[a] = sm[c*33 + w] + 2.f * Dp[c] * x[a];
    }
}

// ============================================================================
extern "C" void kernel_launch(void* const* d_in, const int* in_sizes, int n_in,
                              void* d_out, int out_size)
{
    const float* x     = (const float*)d_in[0];
    const float* A_log = (const float*)d_in[1];
    const float* D     = (const float*)d_in[2];
    const float* xw    = (const float*)d_in[3];
    const float* dtw   = (const float*)d_in[4];
    const float* dtb   = (const float*)d_in[5];
    float* out = (float*)d_out;

    k_xpose<<<BATCH*(HH*WW/64), 256>>>(x);
    k_prep<<<NTOK/128, 128>>>(xw, dtw, dtb);
    k_scan<<<1024, 64>>>(A_log);
    k_comb<<<BATCH*HH*(WW/32), 256>>>(x, D, out);
}

// round 12
// speedup vs baseline: 1.4132x; 1.4132x over previous
#include <cuda_runtime.h>
#include <cstdint>

#define BATCH 4
#define CH    64
#define HH    128
#define WW    128
#define NST   16
#define NTOK  (BATCH*HH*WW)

// ---- scratch (static __device__, allocation-free) ----
__device__ float g_dp[NTOK*CH];   // delta, channels-last [tok][c]
__device__ float g_du[NTOK*CH];   // delta*u
__device__ float g_bc[NTOK*32];   // [tok][Bc(16) | Cc(16)]
__device__ float g_yh[NTOK*CH];   // horizontal scan output
__device__ float g_yv[NTOK*CH];   // vertical scan output

__device__ __forceinline__ float ex2f(float x){
    float r; asm("ex2.approx.ftz.f32 %0, %1;" : "=f"(r) : "f"(x)); return r;
}
__device__ __forceinline__ void cp16(void* dst, const void* src){
    unsigned s = (unsigned)__cvta_generic_to_shared(dst);
    asm volatile("cp.async.cg.shared.global [%0], [%1], 16;\n" :: "r"(s), "l"(src));
}
// ---- packed f32x2 helpers ----
__device__ __forceinline__ unsigned long long pk2(float lo, float hi){
    unsigned long long r; asm("mov.b64 %0, {%1,%2};" : "=l"(r) : "f"(lo), "f"(hi)); return r;
}
__device__ __forceinline__ void upk2(float& lo, float& hi, unsigned long long v){
    asm("mov.b64 {%0,%1}, %2;" : "=f"(lo), "=f"(hi) : "l"(v));
}
__device__ __forceinline__ unsigned long long mul2(unsigned long long a, unsigned long long b){
    unsigned long long r; asm("mul.rn.f32x2 %0, %1, %2;" : "=l"(r) : "l"(a), "l"(b)); return r;
}
__device__ __forceinline__ unsigned long long fmap2(unsigned long long a, unsigned long long b, unsigned long long c){
    unsigned long long r; asm("fma.rn.f32x2 %0, %1, %2, %3;" : "=l"(r) : "l"(a), "l"(b), "l"(c)); return r;
}
__device__ __forceinline__ unsigned long long addp2(unsigned long long a, unsigned long long b){
    unsigned long long r; asm("add.rn.f32x2 %0, %1, %2;" : "=l"(r) : "l"(a), "l"(b)); return r;
}

// ============================================================================
// K1: projection + delta (R6 version, best measured). Block = 1 row (128
// tokens), 256 threads. u staged via cp.async double buffer (16-ch chunks).
// Thread (w2 = tid&63, q = tid>>6): 9 outputs x 2 tokens.
// ============================================================================
__global__ __launch_bounds__(256) void k_prep(
    const float* __restrict__ x,    // [B][C][H][W]
    const float* __restrict__ xw,   // [36][64]
    const float* __restrict__ dtw,  // [64][4]
    const float* __restrict__ dtb)  // [64]
{
    __shared__ __align__(16) float wq[4][CH][12];      // 12.3KB
    __shared__ __align__(16) float proj_sm[128][37];   // 18.9KB
    __shared__ __align__(16) float u_buf[2][16][128];  // 16.0KB
    __shared__ float dtwT[4*CH];                       // 1KB
    __shared__ float dtb_sm[CH];                       // 0.25KB

    const int tid = threadIdx.x;
    const int blk = blockIdx.x;            // 0..511
    const int b   = blk >> 7;
    const int h   = blk & 127;
    const long rowbase = ((long)b*CH*HH + h) * WW;   // x offset at c=0

    auto issue_u = [&](int k, int buf){
        const float* src = x + rowbase + (long)(k*16)*HH*WW;
        #pragma unroll
        for (int r = 0; r < 2; ++r){
            int idx = tid + 256*r;          // 0..511
            int cl = idx >> 5, chk = idx & 31;
            cp16(&u_buf[buf][cl][chk*4], src + (long)cl*HH*WW + chk*4);
        }
    };

    issue_u(0, 0);
    asm volatile("cp.async.commit_group;\n");

    // ---- stage weights (overlaps with first u chunk) ----
    for (int i = tid; i < 36*CH; i += 256){
        int p = i >> 6, c = i & 63;
        wq[p/9][c][p%9] = xw[i];
    }
    if (tid < CH*4){ int d = tid >> 2, r = tid & 3; dtwT[r*CH + d] = dtw[tid]; }
    if (tid < CH)   dtb_sm[tid] = dtb[tid];

    // ---- GEMM ----
    {
        const int w2 = tid & 63, q = tid >> 6;
        float a0[9], a1[9];
        #pragma unroll
        for (int j = 0; j < 9; ++j){ a0[j] = 0.f; a1[j] = 0.f; }

        for (int k = 0; k < 4; ++k){
            if (k < 3) issue_u(k+1, (k+1)&1);
            asm volatile("cp.async.commit_group;\n");
            asm volatile("cp.async.wait_group 1;\n");
            __syncthreads();

            const float (*ub)[128] = u_buf[k&1];
            const int cb = k*16;
            #pragma unroll 4
            for (int cl = 0; cl < 16; ++cl){
                float2 u = *reinterpret_cast<const float2*>(&ub[cl][2*w2]);
                const float4* wp = reinterpret_cast<const float4*>(&wq[q][cb+cl][0]);
                float4 v0 = wp[0], v1 = wp[1];
                float  w8 = wq[q][cb+cl][8];
                a0[0] = fmaf(u.x, v0.x, a0[0]);  a1[0] = fmaf(u.y, v0.x, a1[0]);
                a0[1] = fmaf(u.x, v0.y, a0[1]);  a1[1] = fmaf(u.y, v0.y, a1[1]);
                a0[2] = fmaf(u.x, v0.z, a0[2]);  a1[2] = fmaf(u.y, v0.z, a1[2]);
                a0[3] = fmaf(u.x, v0.w, a0[3]);  a1[3] = fmaf(u.y, v0.w, a1[3]);
                a0[4] = fmaf(u.x, v1.x, a0[4]);  a1[4] = fmaf(u.y, v1.x, a1[4]);
                a0[5] = fmaf(u.x, v1.y, a0[5]);  a1[5] = fmaf(u.y, v1.y, a1[5]);
                a0[6] = fmaf(u.x, v1.z, a0[6]);  a1[6] = fmaf(u.y, v1.z, a1[6]);
                a0[7] = fmaf(u.x, v1.w, a0[7]);  a1[7] = fmaf(u.y, v1.w, a1[7]);
                a0[8] = fmaf(u.x, w8,   a0[8]);  a1[8] = fmaf(u.y, w8,   a1[8]);
            }
            __syncthreads();
        }
        const int pb = 9*q;
        #pragma unroll
        for (int j = 0; j < 9; ++j){
            proj_sm[2*w2  ][pb + j] = a0[j];
            proj_sm[2*w2+1][pb + j] = a1[j];
        }
    }
    __syncthreads();

    const long tok0 = ((long)b*HH + h) << 7;

    // ---- Bc|Cc out, fully coalesced ----
    for (int i = tid; i < 128*32; i += 256){
        int w = i >> 5, j = i & 31;
        g_bc[(tok0 + w)*32 + j] = proj_sm[w][4 + j];
    }

    // ---- delta = softplus(dt_raw @ dtw^T + b); du = delta*u ----
    {
        const int w   = tid & 127;
        const int c0  = (tid >> 7) * 32;
        const float dt0 = proj_sm[w][0], dt1 = proj_sm[w][1];
        const float dt2 = proj_sm[w][2], dt3 = proj_sm[w][3];
        const float* xr = x + rowbase + w;       // + c*HH*WW per channel
        float* dpw = g_dp + (tok0 + w)*CH;
        float* duw = g_du + (tok0 + w)*CH;

        #pragma unroll 2
        for (int cb = c0; cb < c0 + 32; cb += 4){
            float4 dp4, du4;
            #pragma unroll
            for (int cc = 0; cc < 4; ++cc){
                int c = cb + cc;
                float pre = fmaf(dt3, dtwT[192+c],
                            fmaf(dt2, dtwT[128+c],
                            fmaf(dt1, dtwT[ 64+c],
                            fmaf(dt0, dtwT[c], dtb_sm[c]))));
                float e = __expf(-fabsf(pre));
                float delta = __logf(1.f + e) + fmaxf(pre, 0.f);
                float u = xr[(long)c*HH*WW];     // lane=w -> coalesced
                (&dp4.x)[cc] = delta;
                (&du4.x)[cc] = delta * u;
            }
            *reinterpret_cast<float4*>(dpw + cb) = dp4;
            *reinterpret_cast<float4*>(duw + cb) = du4;
        }
    }
}

// ============================================================================
// K2: selective scan, packed f32x2 math (R5 version). Block = 1 sequence
// (64 threads, thread = channel). 0..511 horizontal, 512..1023 vertical.
// ============================================================================
__global__ __launch_bounds__(64) void k_scan(const float* __restrict__ A_log)
{
    // 2 buffers x (16 tok x (64 dp + 64 du + 32 bc)) = 2*2560 floats = 20KB
    __shared__ __align__(16) float sm[2*2560];

    const int tid = threadIdx.x;            // channel
    const int S   = blockIdx.x;
    const int vert = (S >= 512);
    const int s    = vert ? S - 512 : S;
    const int b = s >> 7, r = s & 127;

    long tok0; int tstride;
    if (!vert){ tok0 = ((long)b*HH + r)*WW; tstride = 1;  }
    else      { tok0 = (long)b*HH*WW + r;   tstride = WW; }
    float* yout = vert ? g_yv : g_yh;

    // A with log2(e) folded in, packed in pairs: dA = exp2(delta * A2[n])
    unsigned long long A2p[8], hsp[8];
    #pragma unroll
    for (int j = 0; j < 8; ++j){
        float alo = -__expf(A_log[tid*NST + 2*j    ]) * 1.4426950408889634f;
        float ahi = -__expf(A_log[tid*NST + 2*j + 1]) * 1.4426950408889634f;
        A2p[j] = pk2(alo, ahi);
        hsp[j] = 0ull;
    }

    auto issue = [&](int t, int bufidx){
        float* dst = sm + bufidx*2560;
        const int tn = t*16;
        for (int k = tid; k < 256; k += 64){
            int l = k >> 4, q = k & 15;
            long tok = tok0 + (long)(tn + l)*tstride;
            cp16(dst +        l*64 + q*4, g_dp + tok*64 + q*4);
            cp16(dst + 1024 + l*64 + q*4, g_du + tok*64 + q*4);
        }
        for (int k = tid; k < 128; k += 64){
            int l = k >> 3, q = k & 7;
            long tok = tok0 + (long)(tn + l)*tstride;
            cp16(dst + 2048 + l*32 + q*4, g_bc + tok*32 + q*4);
        }
    };

    issue(0, 0);
    asm volatile("cp.async.commit_group;\n");

    for (int t = 0; t < 8; ++t){
        if (t < 7) issue(t+1, (t+1)&1);
        asm volatile("cp.async.commit_group;\n");
        asm volatile("cp.async.wait_group 1;\n");
        __syncthreads();

        const float* bp = sm + (t&1)*2560;
        #pragma unroll 2
        for (int l = 0; l < 16; ++l){
            float delta = bp[l*64 + tid];
            float duv   = bp[1024 + l*64 + tid];
            unsigned long long d2  = pk2(delta, delta);
            unsigned long long uv2 = pk2(duv, duv);

            const ulonglong2* q16 = reinterpret_cast<const ulonglong2*>(bp + 2048 + l*32);
            ulonglong2 B01 = q16[0], B23 = q16[1], B45 = q16[2], B67 = q16[3];
            ulonglong2 C01 = q16[4], C23 = q16[5], C45 = q16[6], C67 = q16[7];
            unsigned long long bn2[8] = {B01.x,B01.y,B23.x,B23.y,B45.x,B45.y,B67.x,B67.y};
            unsigned long long cn2[8] = {C01.x,C01.y,C23.x,C23.y,C45.x,C45.y,C67.x,C67.y};

            unsigned long long ya0=0ull, ya1=0ull, ya2=0ull, ya3=0ull;
            #pragma unroll
            for (int j = 0; j < 8; ++j){
                unsigned long long xa = mul2(d2, A2p[j]);
                float lo, hi; upk2(lo, hi, xa);
                unsigned long long dA2 = pk2(ex2f(lo), ex2f(hi));
                unsigned long long db  = mul2(uv2, bn2[j]);
                hsp[j] = fmap2(dA2, hsp[j], db);
                unsigned long long* ya = (j&2) ? ((j&1)? &ya3 : &ya2)
                                               : ((j&1)? &ya1 : &ya0);
                *ya = fmap2(hsp[j], cn2[j], *ya);
            }
            unsigned long long sA = addp2(ya0, ya1);
            unsigned long long sB = addp2(ya2, ya3);
            unsigned long long sT = addp2(sA, sB);
            float slo, shi; upk2(slo, shi, sT);
            yout[(tok0 + (long)(t*16 + l)*tstride)*64 + tid] = slo + shi;  // coalesced
        }
        __syncthreads();
    }
}

// ============================================================================
// K3: out[b,c,h,w] = y_h + y_v + 2*D[c]*x. Tile = 64 tokens x 64 channels,
// float4 on BOTH global sides (LDG.128 / STG.128), smem transpose.
// grid = 1024, 256 threads.
// ============================================================================
__global__ __launch_bounds__(256) void k_comb(
    const float* __restrict__ x, const float* __restrict__ Dp,
    float* __restrict__ out)
{
    __shared__ float sm[CH][65];               // [c][w]
    const int tid = threadIdx.x;
    const int blk = blockIdx.x;                // b*256 + h*2 + whalf
    const int b   = blk >> 8;
    const int h   = (blk >> 1) & 127;
    const int w0  = (blk & 1) << 6;
    const long tokb = (((long)b*HH + h) << 7) + w0;

    // ---- phase A: yh+yv -> sm[c][w], float4 global reads ----
    #pragma unroll
    for (int it = 0; it < 4; ++it){
        int i  = tid + it*256;                 // 0..1023
        int w  = i >> 4, c4 = i & 15;          // lanes: consecutive c4 -> 256B/half-warp
        long o = ((tokb + w) << 6) + c4*4;
        float4 a = *reinterpret_cast<const float4*>(g_yh + o);
        float4 v = *reinterpret_cast<const float4*>(g_yv + o);
        sm[4*c4+0][w] = a.x + v.x;
        sm[4*c4+1][w] = a.y + v.y;
        sm[4*c4+2][w] = a.z + v.z;
        sm[4*c4+3][w] = a.w + v.w;
    }
    __syncthreads();

    // ---- phase B: out = sm + 2*D*x, float4 global read+write ----
    #pragma unroll
    for (int it = 0; it < 4; ++it){
        int i  = tid + it*256;
        int c  = i >> 4, w4 = i & 15;          // lanes: consecutive w4 -> 256B/half-warp
        long a = (((long)(b*CH + c)*HH + h) << 7) + w0 + 4*w4;
        float4 xv = *reinterpret_cast<const float4*>(x + a);
        float  d2 = 2.f * Dp[c];
        float4 o4;
        o4.x = sm[c][4*w4+0] + d2 * xv.x;
        o4.y = sm[c][4*w4+1] + d2 * xv.y;
        o4.z = sm[c][4*w4+2] + d2 * xv.z;
        o4.w = sm[c][4*w4+3] + d2 * xv.w;
        *reinterpret_cast<float4*>(out + a) = o4;
    }
}

// ============================================================================
extern "C" void kernel_launch(void* const* d_in, const int* in_sizes, int n_in,
                              void* d_out, int out_size)
{
    const float* x     = (const float*)d_in[0];
    const float* A_log = (const float*)d_in[1];
    const float* D     = (const float*)d_in[2];
    const float* xw    = (const float*)d_in[3];
    const float* dtw   = (const float*)d_in[4];
    const float* dtb   = (const float*)d_in[5];
    float* out = (float*)d_out;

    k_prep<<<BATCH*HH, 256>>>(x, xw, dtw, dtb);
    k_scan<<<1024, 64>>>(A_log);
    k_comb<<<BATCH*HH*2, 256>>>(x, D, out);
}

// round 13
// speedup vs baseline: 1.4448x; 1.0224x over previous
#include <cuda_runtime.h>
#include <cstdint>

#define BATCH 4
#define CH    64
#define HH    128
#define WW    128
#define NST   16
#define NTOK  (BATCH*HH*WW)

// ---- scratch (static __device__, allocation-free) ----
__device__ float g_dp[NTOK*CH];   // delta, channels-last [tok][c]
__device__ float g_du[NTOK*CH];   // delta*u
__device__ float g_bc[NTOK*32];   // [tok][Bc(16) | Cc(16)]
__device__ float g_yh[NTOK*CH];   // horizontal scan output
__device__ float g_yv[NTOK*CH];   // vertical scan output

__device__ __forceinline__ float ex2f(float x){
    float r; asm("ex2.approx.ftz.f32 %0, %1;" : "=f"(r) : "f"(x)); return r;
}
__device__ __forceinline__ void cp16(void* dst, const void* src){
    unsigned s = (unsigned)__cvta_generic_to_shared(dst);
    asm volatile("cp.async.cg.shared.global [%0], [%1], 16;\n" :: "r"(s), "l"(src));
}
// ---- packed f32x2 helpers ----
__device__ __forceinline__ unsigned long long pk2(float lo, float hi){
    unsigned long long r; asm("mov.b64 %0, {%1,%2};" : "=l"(r) : "f"(lo), "f"(hi)); return r;
}
__device__ __forceinline__ void upk2(float& lo, float& hi, unsigned long long v){
    asm("mov.b64 {%0,%1}, %2;" : "=f"(lo), "=f"(hi) : "l"(v));
}
__device__ __forceinline__ unsigned long long mul2(unsigned long long a, unsigned long long b){
    unsigned long long r; asm("mul.rn.f32x2 %0, %1, %2;" : "=l"(r) : "l"(a), "l"(b)); return r;
}
__device__ __forceinline__ unsigned long long fmap2(unsigned long long a, unsigned long long b, unsigned long long c){
    unsigned long long r; asm("fma.rn.f32x2 %0, %1, %2, %3;" : "=l"(r) : "l"(a), "l"(b), "l"(c)); return r;
}
__device__ __forceinline__ unsigned long long addp2(unsigned long long a, unsigned long long b){
    unsigned long long r; asm("add.rn.f32x2 %0, %1, %2;" : "=l"(r) : "l"(a), "l"(b)); return r;
}

// ============================================================================
// K1: projection + delta. Block = 1 row (128 tokens), 256 threads.
// GEMM identical to R6/R12. Phase 2 now stages delta/du through smem so all
// g_dp/g_du stores are full-line coalesced STG.128.
// ============================================================================
__global__ __launch_bounds__(256) void k_prep(
    const float* __restrict__ x,    // [B][C][H][W]
    const float* __restrict__ xw,   // [36][64]
    const float* __restrict__ dtw,  // [64][4]
    const float* __restrict__ dtb)  // [64]
{
    __shared__ __align__(16) float wq[4][CH][12];      // 12.3KB
    __shared__ __align__(16) float proj_sm[128][37];   // 18.9KB (reused as stage)
    __shared__ __align__(16) float u_buf[2][16][128];  // 16.0KB
    __shared__ float dtwT[4*CH];                       // 1KB
    __shared__ float dtb_sm[CH];                       // 0.25KB

    const int tid = threadIdx.x;
    const int blk = blockIdx.x;            // 0..511
    const int b   = blk >> 7;
    const int h   = blk & 127;
    const long rowbase = ((long)b*CH*HH + h) * WW;   // x offset at c=0

    auto issue_u = [&](int k, int buf){
        const float* src = x + rowbase + (long)(k*16)*HH*WW;
        #pragma unroll
        for (int r = 0; r < 2; ++r){
            int idx = tid + 256*r;          // 0..511
            int cl = idx >> 5, chk = idx & 31;
            cp16(&u_buf[buf][cl][chk*4], src + (long)cl*HH*WW + chk*4);
        }
    };

    issue_u(0, 0);
    asm volatile("cp.async.commit_group;\n");

    // ---- stage weights (overlaps with first u chunk) ----
    for (int i = tid; i < 36*CH; i += 256){
        int p = i >> 6, c = i & 63;
        wq[p/9][c][p%9] = xw[i];
    }
    if (tid < CH*4){ int d = tid >> 2, r = tid & 3; dtwT[r*CH + d] = dtw[tid]; }
    if (tid < CH)   dtb_sm[tid] = dtb[tid];

    // ---- GEMM ----
    {
        const int w2 = tid & 63, q = tid >> 6;
        float a0[9], a1[9];
        #pragma unroll
        for (int j = 0; j < 9; ++j){ a0[j] = 0.f; a1[j] = 0.f; }

        for (int k = 0; k < 4; ++k){
            if (k < 3) issue_u(k+1, (k+1)&1);
            asm volatile("cp.async.commit_group;\n");
            asm volatile("cp.async.wait_group 1;\n");
            __syncthreads();

            const float (*ub)[128] = u_buf[k&1];
            const int cb = k*16;
            #pragma unroll 4
            for (int cl = 0; cl < 16; ++cl){
                float2 u = *reinterpret_cast<const float2*>(&ub[cl][2*w2]);
                const float4* wp = reinterpret_cast<const float4*>(&wq[q][cb+cl][0]);
                float4 v0 = wp[0], v1 = wp[1];
                float  w8 = wq[q][cb+cl][8];
                a0[0] = fmaf(u.x, v0.x, a0[0]);  a1[0] = fmaf(u.y, v0.x, a1[0]);
                a0[1] = fmaf(u.x, v0.y, a0[1]);  a1[1] = fmaf(u.y, v0.y, a1[1]);
                a0[2] = fmaf(u.x, v0.z, a0[2]);  a1[2] = fmaf(u.y, v0.z, a1[2]);
                a0[3] = fmaf(u.x, v0.w, a0[3]);  a1[3] = fmaf(u.y, v0.w, a1[3]);
                a0[4] = fmaf(u.x, v1.x, a0[4]);  a1[4] = fmaf(u.y, v1.x, a1[4]);
                a0[5] = fmaf(u.x, v1.y, a0[5]);  a1[5] = fmaf(u.y, v1.y, a1[5]);
                a0[6] = fmaf(u.x, v1.z, a0[6]);  a1[6] = fmaf(u.y, v1.z, a1[6]);
                a0[7] = fmaf(u.x, v1.w, a0[7]);  a1[7] = fmaf(u.y, v1.w, a1[7]);
                a0[8] = fmaf(u.x, w8,   a0[8]);  a1[8] = fmaf(u.y, w8,   a1[8]);
            }
            __syncthreads();
        }
        const int pb = 9*q;
        #pragma unroll
        for (int j = 0; j < 9; ++j){
            proj_sm[2*w2  ][pb + j] = a0[j];
            proj_sm[2*w2+1][pb + j] = a1[j];
        }
    }
    __syncthreads();

    const long tok0 = ((long)b*HH + h) << 7;

    // ---- Bc|Cc out, fully coalesced ----
    for (int i = tid; i < 128*32; i += 256){
        int w = i >> 5, j = i & 31;
        g_bc[(tok0 + w)*32 + j] = proj_sm[w][4 + j];
    }

    // ---- phase 2: delta = softplus(...), du = delta*u, staged+coalesced ----
    {
        const int w   = tid & 127;
        const int sub = tid >> 7;              // 0/1: which 16-channel half of chunk
        const float dt0 = proj_sm[w][0], dt1 = proj_sm[w][1];
        const float dt2 = proj_sm[w][2], dt3 = proj_sm[w][3];
        __syncthreads();                       // all proj_sm reads done; reuse as stage
        float* stage = &proj_sm[0][0];         // need 128*33=4224 <= 4736 floats

        #pragma unroll 1
        for (int chunk = 0; chunk < 2; ++chunk){
            const int cbase = chunk*32 + sub*16;
            float delta_r[16];
            // compute: lanes = consecutive w -> coalesced x loads, pad-33 stage
            #pragma unroll 4
            for (int j = 0; j < 16; ++j){
                int c = cbase + j;
                float pre = fmaf(dt3, dtwT[192+c],
                            fmaf(dt2, dtwT[128+c],
                            fmaf(dt1, dtwT[ 64+c],
                            fmaf(dt0, dtwT[c], dtb_sm[c]))));
                float e = __expf(-fabsf(pre));
                float delta = __logf(1.f + e) + fmaxf(pre, 0.f);
                delta_r[j] = delta;
                float u = x[rowbase + (long)c*HH*WW + w];   // coalesced
                stage[w*33 + sub*16 + j] = delta * u;       // du
            }
            __syncthreads();
            // du store: full-line coalesced (8 x float4 = 128B per token)
            for (int i = tid; i < 1024; i += 256){
                int w2 = i >> 3, j4 = i & 7;
                const float* sp = stage + w2*33 + j4*4;
                float4 v = make_float4(sp[0], sp[1], sp[2], sp[3]);
                *reinterpret_cast<float4*>(g_du + ((tok0 + w2) << 6) + chunk*32 + j4*4) = v;
            }
            __syncthreads();
            // dp stage from regs (no loads), then coalesced store
            #pragma unroll
            for (int j = 0; j < 16; ++j)
                stage[w*33 + sub*16 + j] = delta_r[j];
            __syncthreads();
            for (int i = tid; i < 1024; i += 256){
                int w2 = i >> 3, j4 = i & 7;
                const float* sp = stage + w2*33 + j4*4;
                float4 v = make_float4(sp[0], sp[1], sp[2], sp[3]);
                *reinterpret_cast<float4*>(g_dp + ((tok0 + w2) << 6) + chunk*32 + j4*4) = v;
            }
            __syncthreads();
        }
    }
}

// ============================================================================
// K2: selective scan, packed f32x2 math (R5 version). Block = 1 sequence
// (64 threads, thread = channel). 0..511 horizontal, 512..1023 vertical.
// ============================================================================
__global__ __launch_bounds__(64) void k_scan(const float* __restrict__ A_log)
{
    // 2 buffers x (16 tok x (64 dp + 64 du + 32 bc)) = 2*2560 floats = 20KB
    __shared__ __align__(16) float sm[2*2560];

    const int tid = threadIdx.x;            // channel
    const int S   = blockIdx.x;
    const int vert = (S >= 512);
    const int s    = vert ? S - 512 : S;
    const int b = s >> 7, r = s & 127;

    long tok0; int tstride;
    if (!vert){ tok0 = ((long)b*HH + r)*WW; tstride = 1;  }
    else      { tok0 = (long)b*HH*WW + r;   tstride = WW; }
    float* yout = vert ? g_yv : g_yh;

    // A with log2(e) folded in, packed in pairs: dA = exp2(delta * A2[n])
    unsigned long long A2p[8], hsp[8];
    #pragma unroll
    for (int j = 0; j < 8; ++j){
        float alo = -__expf(A_log[tid*NST + 2*j    ]) * 1.4426950408889634f;
        float ahi = -__expf(A_log[tid*NST + 2*j + 1]) * 1.4426950408889634f;
        A2p[j] = pk2(alo, ahi);
        hsp[j] = 0ull;
    }

    auto issue = [&](int t, int bufidx){
        float* dst = sm + bufidx*2560;
        const int tn = t*16;
        for (int k = tid; k < 256; k += 64){
            int l = k >> 4, q = k & 15;
            long tok = tok0 + (long)(tn + l)*tstride;
            cp16(dst +        l*64 + q*4, g_dp + tok*64 + q*4);
            cp16(dst + 1024 + l*64 + q*4, g_du + tok*64 + q*4);
        }
        for (int k = tid; k < 128; k += 64){
            int l = k >> 3, q = k & 7;
            long tok = tok0 + (long)(tn + l)*tstride;
            cp16(dst + 2048 + l*32 + q*4, g_bc + tok*32 + q*4);
        }
    };

    issue(0, 0);
    asm volatile("cp.async.commit_group;\n");

    for (int t = 0; t < 8; ++t){
        if (t < 7) issue(t+1, (t+1)&1);
        asm volatile("cp.async.commit_group;\n");
        asm volatile("cp.async.wait_group 1;\n");
        __syncthreads();

        const float* bp = sm + (t&1)*2560;
        #pragma unroll 2
        for (int l = 0; l < 16; ++l){
            float delta = bp[l*64 + tid];
            float duv   = bp[1024 + l*64 + tid];
            unsigned long long d2  = pk2(delta, delta);
            unsigned long long uv2 = pk2(duv, duv);

            const ulonglong2* q16 = reinterpret_cast<const ulonglong2*>(bp + 2048 + l*32);
            ulonglong2 B01 = q16[0], B23 = q16[1], B45 = q16[2], B67 = q16[3];
            ulonglong2 C01 = q16[4], C23 = q16[5], C45 = q16[6], C67 = q16[7];
            unsigned long long bn2[8] = {B01.x,B01.y,B23.x,B23.y,B45.x,B45.y,B67.x,B67.y};
            unsigned long long cn2[8] = {C01.x,C01.y,C23.x,C23.y,C45.x,C45.y,C67.x,C67.y};

            unsigned long long ya0=0ull, ya1=0ull, ya2=0ull, ya3=0ull;
            #pragma unroll
            for (int j = 0; j < 8; ++j){
                unsigned long long xa = mul2(d2, A2p[j]);
                float lo, hi; upk2(lo, hi, xa);
                unsigned long long dA2 = pk2(ex2f(lo), ex2f(hi));
                unsigned long long db  = mul2(uv2, bn2[j]);
                hsp[j] = fmap2(dA2, hsp[j], db);
                unsigned long long* ya = (j&2) ? ((j&1)? &ya3 : &ya2)
                                               : ((j&1)? &ya1 : &ya0);
                *ya = fmap2(hsp[j], cn2[j], *ya);
            }
            unsigned long long sA = addp2(ya0, ya1);
            unsigned long long sB = addp2(ya2, ya3);
            unsigned long long sT = addp2(sA, sB);
            float slo, shi; upk2(slo, shi, sT);
            yout[(tok0 + (long)(t*16 + l)*tstride)*64 + tid] = slo + shi;  // coalesced
        }
        __syncthreads();
    }
}

// ============================================================================
// K3: out[b,c,h,w] = y_h + y_v + 2*D[c]*x. Tile = 64 tokens x 64 channels,
// float4 on BOTH global sides (LDG.128 / STG.128), smem transpose.
// grid = 1024, 256 threads.
// ============================================================================
__global__ __launch_bounds__(256) void k_comb(
    const float* __restrict__ x, const float* __restrict__ Dp,
    float* __restrict__ out)
{
    __shared__ float sm[CH][65];               // [c][w]
    const int tid = threadIdx.x;
    const int blk = blockIdx.x;                // b*256 + h*2 + whalf
    const int b   = blk >> 8;
    const int h   = (blk >> 1) & 127;
    const int w0  = (blk & 1) << 6;
    const long tokb = (((long)b*HH + h) << 7) + w0;

    // ---- phase A: yh+yv -> sm[c][w], float4 global reads ----
    #pragma unroll
    for (int it = 0; it < 4; ++it){
        int i  = tid + it*256;                 // 0..1023
        int w  = i >> 4, c4 = i & 15;          // lanes: consecutive c4 -> 256B/half-warp
        long o = ((tokb + w) << 6) + c4*4;
        float4 a = *reinterpret_cast<const float4*>(g_yh + o);
        float4 v = *reinterpret_cast<const float4*>(g_yv + o);
        sm[4*c4+0][w] = a.x + v.x;
        sm[4*c4+1][w] = a.y + v.y;
        sm[4*c4+2][w] = a.z + v.z;
        sm[4*c4+3][w] = a.w + v.w;
    }
    __syncthreads();

    // ---- phase B: out = sm + 2*D*x, float4 global read+write ----
    #pragma unroll
    for (int it = 0; it < 4; ++it){
        int i  = tid + it*256;
        int c  = i >> 4, w4 = i & 15;          // lanes: consecutive w4 -> 256B/half-warp
        long a = (((long)(b*CH + c)*HH + h) << 7) + w0 + 4*w4;
        float4 xv = *reinterpret_cast<const float4*>(x + a);
        float  d2 = 2.f * Dp[c];
        float4 o4;
        o4.x = sm[c][4*w4+0] + d2 * xv.x;
        o4.y = sm[c][4*w4+1] + d2 * xv.y;
        o4.z = sm[c][4*w4+2] + d2 * xv.z;
        o4.w = sm[c][4*w4+3] + d2 * xv.w;
        *reinterpret_cast<float4*>(out + a) = o4;
    }
}

// ============================================================================
extern "C" void kernel_launch(void* const* d_in, const int* in_sizes, int n_in,
                              void* d_out, int out_size)
{
    const float* x     = (const float*)d_in[0];
    const float* A_log = (const float*)d_in[1];
    const float* D     = (const float*)d_in[2];
    const float* xw    = (const float*)d_in[3];
    const float* dtw   = (const float*)d_in[4];
    const float* dtb   = (const float*)d_in[5];
    float* out = (float*)d_out;

    k_prep<<<BATCH*HH, 256>>>(x, xw, dtw, dtb);
    k_scan<<<1024, 64>>>(A_log);
    k_comb<<<BATCH*HH*2, 256>>>(x, D, out);
}